// round 5
// baseline (speedup 1.0000x reference)
#include <cuda_runtime.h>
#include <math.h>
#include <stdint.h>

// Problem constants
#define BATCH   4
#define TSEQ    2048
#define NHEAD   16
#define HSIZE   64
#define CEMB    1024
#define MROWS   (BATCH*TSEQ)   // 8192

// Scratch (device globals: allocation-free rule)
__device__ float g_q[(size_t)BATCH * NHEAD * TSEQ * HSIZE];   // [B,H,T,D], q pre-scaled
__device__ float g_k[(size_t)BATCH * NHEAD * TSEQ * HSIZE];   // [B,H,T,D]
__device__ float g_v[(size_t)BATCH * NHEAD * TSEQ * HSIZE];   // [B,H,D,T]  (transposed!)
__device__ float g_attn[(size_t)MROWS * CEMB];                // [B*T, C]
__device__ float g_wt_qkv[(size_t)3 * CEMB * CEMB];           // [3C, C] K-major
__device__ float g_wt_proj[(size_t)CEMB * CEMB];              // [C, C]  K-major

// ---------------------------------------------------------------------------
// tf32 helpers (legacy mma.sync path — valid on plain sm_103 PTX target)
// ---------------------------------------------------------------------------
__device__ __forceinline__ uint32_t f2tf32(float x) {
    uint32_t r;
    asm("cvt.rna.tf32.f32 %0, %1;" : "=r"(r) : "f"(x));
    return r;
}
__device__ __forceinline__ void mma_tf32(float& c0, float& c1, float& c2, float& c3,
                                         uint32_t a0, uint32_t a1, uint32_t a2, uint32_t a3,
                                         uint32_t b0, uint32_t b1) {
    asm volatile("mma.sync.aligned.m16n8k8.row.col.f32.tf32.tf32.f32 "
                 "{%0,%1,%2,%3}, {%4,%5,%6,%7}, {%8,%9}, {%0,%1,%2,%3};"
                 : "+f"(c0), "+f"(c1), "+f"(c2), "+f"(c3)
                 : "r"(a0), "r"(a1), "r"(a2), "r"(a3), "r"(b0), "r"(b1));
}

// ---------------------------------------------------------------------------
// Weight transpose: in [R][C] row-major -> out [C][R] row-major
// ---------------------------------------------------------------------------
__global__ __launch_bounds__(256) void transpose_k(const float* __restrict__ in,
                                                   float* __restrict__ out, int R, int C)
{
    __shared__ float t[32][33];
    int bx = blockIdx.x * 32, by = blockIdx.y * 32;
#pragma unroll
    for (int i = 0; i < 32; i += 8)
        t[threadIdx.y + i][threadIdx.x] = in[(size_t)(by + threadIdx.y + i) * C + bx + threadIdx.x];
    __syncthreads();
#pragma unroll
    for (int i = 0; i < 32; i += 8)
        out[(size_t)(bx + threadIdx.y + i) * R + by + threadIdx.x] = t[threadIdx.x][threadIdx.y + i];
}

// ---------------------------------------------------------------------------
// tf32 tensor-core GEMM, mma.sync m16n8k8, with register-prefetch pipeline.
// C[M,N] = A[M,K]*Bt[N,K]^T (+bias). Block 256 (8 warps), tile 128x128.
// mode 0: scatter g_q (x0.125)/g_k [B,H,T,D]; g_v [B,H,D,T]. mode 1: C=acc+bias.
// ---------------------------------------------------------------------------
__global__ __launch_bounds__(256) void gemm_mma(
    const float* __restrict__ A, const float* __restrict__ Bt,
    const float* __restrict__ bias, float* __restrict__ C,
    int M, int N, int K, int mode)
{
    __shared__ float As[128][36];
    __shared__ float Bs[128][36];

    const int tid  = threadIdx.x;
    const int wid  = tid >> 5;
    const int lane = tid & 31;
    const int g    = lane >> 2;
    const int t    = lane & 3;
    const int wm   = wid & 3;
    const int wn   = wid >> 2;
    const int m0 = blockIdx.y * 128;
    const int n0 = blockIdx.x * 128;

    const int lr = tid >> 3;
    const int lk = (tid & 7) * 4;

    float c[2][8][4];
#pragma unroll
    for (int mt = 0; mt < 2; ++mt)
#pragma unroll
        for (int nt = 0; nt < 8; ++nt)
#pragma unroll
            for (int j = 0; j < 4; ++j) c[mt][nt][j] = 0.f;

    // prefetch buffers (chunk k0=0)
    float4 pa[4], pb[4];
#pragma unroll
    for (int i = 0; i < 4; ++i) {
        int r = lr + i * 32;
        pa[i] = *(const float4*)(A + (size_t)(m0 + r) * K + lk);
        pb[i] = *(const float4*)(Bt + (size_t)(n0 + r) * K + lk);
    }

    for (int k0 = 0; k0 < K; k0 += 32) {
        // store prefetched chunk (tf32-rounded)
#pragma unroll
        for (int i = 0; i < 4; ++i) {
            int r = lr + i * 32;
            float4 ac, bc;
            ac.x = __uint_as_float(f2tf32(pa[i].x)); ac.y = __uint_as_float(f2tf32(pa[i].y));
            ac.z = __uint_as_float(f2tf32(pa[i].z)); ac.w = __uint_as_float(f2tf32(pa[i].w));
            bc.x = __uint_as_float(f2tf32(pb[i].x)); bc.y = __uint_as_float(f2tf32(pb[i].y));
            bc.z = __uint_as_float(f2tf32(pb[i].z)); bc.w = __uint_as_float(f2tf32(pb[i].w));
            *(float4*)&As[r][lk] = ac;
            *(float4*)&Bs[r][lk] = bc;
        }
        __syncthreads();

        // issue next chunk's global loads (hidden behind compute)
        if (k0 + 32 < K) {
#pragma unroll
            for (int i = 0; i < 4; ++i) {
                int r = lr + i * 32;
                pa[i] = *(const float4*)(A + (size_t)(m0 + r) * K + k0 + 32 + lk);
                pb[i] = *(const float4*)(Bt + (size_t)(n0 + r) * K + k0 + 32 + lk);
            }
        }

#pragma unroll
        for (int kt = 0; kt < 4; ++kt) {
            const int kb = kt * 8;
            uint32_t bf[8][2];
#pragma unroll
            for (int nt = 0; nt < 8; ++nt) {
                int n = wn * 64 + nt * 8 + g;
                bf[nt][0] = __float_as_uint(Bs[n][kb + t]);
                bf[nt][1] = __float_as_uint(Bs[n][kb + t + 4]);
            }
#pragma unroll
            for (int mt = 0; mt < 2; ++mt) {
                int mb = wm * 32 + mt * 16;
                uint32_t a0 = __float_as_uint(As[mb + g][kb + t]);
                uint32_t a1 = __float_as_uint(As[mb + g + 8][kb + t]);
                uint32_t a2 = __float_as_uint(As[mb + g][kb + t + 4]);
                uint32_t a3 = __float_as_uint(As[mb + g + 8][kb + t + 4]);
#pragma unroll
                for (int nt = 0; nt < 8; ++nt)
                    mma_tf32(c[mt][nt][0], c[mt][nt][1], c[mt][nt][2], c[mt][nt][3],
                             a0, a1, a2, a3, bf[nt][0], bf[nt][1]);
            }
        }
        __syncthreads();
    }

    const int nbase = n0 + wn * 64;
    if (mode == 0) {
        const int which = nbase >> 10;
        const int h = (nbase & 1023) >> 6;
#pragma unroll
        for (int mt = 0; mt < 2; ++mt) {
            int r0 = m0 + wm * 32 + mt * 16 + g;
            int bb0 = r0 >> 11, tt0 = r0 & (TSEQ - 1);
            int r1 = r0 + 8;
            int bb1 = r1 >> 11, tt1 = r1 & (TSEQ - 1);
            if (which == 2) {
                float* base0 = g_v + ((size_t)(bb0 * NHEAD + h)) * HSIZE * TSEQ;
                float* base1 = g_v + ((size_t)(bb1 * NHEAD + h)) * HSIZE * TSEQ;
#pragma unroll
                for (int nt = 0; nt < 8; ++nt) {
                    int d = nt * 8 + 2 * t;
                    base0[(size_t)d * TSEQ + tt0]       = c[mt][nt][0];
                    base0[(size_t)(d + 1) * TSEQ + tt0] = c[mt][nt][1];
                    base1[(size_t)d * TSEQ + tt1]       = c[mt][nt][2];
                    base1[(size_t)(d + 1) * TSEQ + tt1] = c[mt][nt][3];
                }
            } else {
                const float sc = (which == 0) ? 0.125f : 1.0f;
                float* base = (which == 0) ? g_q : g_k;
                float* d0 = base + (((size_t)(bb0 * NHEAD + h) * TSEQ) + tt0) * HSIZE;
                float* d1 = base + (((size_t)(bb1 * NHEAD + h) * TSEQ) + tt1) * HSIZE;
#pragma unroll
                for (int nt = 0; nt < 8; ++nt) {
                    int d = nt * 8 + 2 * t;
                    float2 v0 = {c[mt][nt][0] * sc, c[mt][nt][1] * sc};
                    float2 v1 = {c[mt][nt][2] * sc, c[mt][nt][3] * sc};
                    *(float2*)(d0 + d) = v0;
                    *(float2*)(d1 + d) = v1;
                }
            }
        }
    } else {
#pragma unroll
        for (int mt = 0; mt < 2; ++mt) {
            int r0 = m0 + wm * 32 + mt * 16 + g;
#pragma unroll
            for (int nt = 0; nt < 8; ++nt) {
                int n = nbase + nt * 8 + 2 * t;
                float2 bv = *(const float2*)(bias + n);
                float2 v0 = {c[mt][nt][0] + bv.x, c[mt][nt][1] + bv.y};
                float2 v1 = {c[mt][nt][2] + bv.x, c[mt][nt][3] + bv.y};
                *(float2*)(C + (size_t)r0 * N + n) = v0;
                *(float2*)(C + (size_t)(r0 + 8) * N + n) = v1;
            }
        }
    }
}

// ---------------------------------------------------------------------------
// Tensor-core causal flash attention (tf32 mma.sync), 128-key tiles.
// CTA: 128 queries of one (b,h). 8 warps x 16 query rows (warp-local softmax).
// Smem: QP [128][132] (Q stage cols 0..63, then P cols 0..127),
//       Ks [128][68] (key x dim), Vs [64][132] (dim x key, from g_v [B,H,D,T]).
// 2 syncthreads per 128 keys. Dyn smem = 136192 B.
// ---------------------------------------------------------------------------
#define QP_PAD 132
#define K_PAD  68
__global__ __launch_bounds__(256) void attn_mma()
{
    extern __shared__ float sm[];
    float* Qs = sm;                        // [128][QP_PAD]  (aliased by Ps)
    float* Ks = sm + 128 * QP_PAD;         // [128][K_PAD]
    float* Vs = Ks + 128 * K_PAD;          // [64][QP_PAD]
    float* Ps = Qs;

    const int tid  = threadIdx.x;
    const int wid  = tid >> 5;
    const int lane = tid & 31;
    const int g    = lane >> 2;
    const int t    = lane & 3;
    const int mb   = wid * 16;
    const int bh   = blockIdx.y;
    const int qb   = gridDim.x - 1 - blockIdx.x;   // reversed: heavy CTAs first
    const int q0   = qb * 128;

    // stage Q tile [128][64] -> smem (tf32-rounded)
    const float* Qg = g_q + ((size_t)bh * TSEQ + q0) * HSIZE;
#pragma unroll
    for (int i = 0; i < 8; ++i) {
        int f = tid + i * 256;
        int r = f >> 4, c4 = (f & 15) * 4;
        float4 v = *(const float4*)(Qg + (size_t)r * HSIZE + c4);
        v.x = __uint_as_float(f2tf32(v.x)); v.y = __uint_as_float(f2tf32(v.y));
        v.z = __uint_as_float(f2tf32(v.z)); v.w = __uint_as_float(f2tf32(v.w));
        *(float4*)&Qs[r * QP_PAD + c4] = v;
    }
    __syncthreads();

    // Q fragments -> registers
    uint32_t qa[8][4];
#pragma unroll
    for (int kb = 0; kb < 8; ++kb) {
        qa[kb][0] = __float_as_uint(Qs[(mb + g) * QP_PAD + kb * 8 + t]);
        qa[kb][1] = __float_as_uint(Qs[(mb + g + 8) * QP_PAD + kb * 8 + t]);
        qa[kb][2] = __float_as_uint(Qs[(mb + g) * QP_PAD + kb * 8 + t + 4]);
        qa[kb][3] = __float_as_uint(Qs[(mb + g + 8) * QP_PAD + kb * 8 + t + 4]);
    }
    __syncthreads();   // Qs now free for P reuse

    float o[8][4];
#pragma unroll
    for (int nt = 0; nt < 8; ++nt)
#pragma unroll
        for (int j = 0; j < 4; ++j) o[nt][j] = 0.f;
    float m0 = -INFINITY, m1 = -INFINITY, l0 = 0.f, l1 = 0.f;

    const int row0 = q0 + mb + g;
    const int row1 = row0 + 8;

    const float* Kg = g_k + (size_t)bh * TSEQ * HSIZE;
    const float* Vg = g_v + (size_t)bh * HSIZE * TSEQ;

    for (int jt = 0; jt <= qb; ++jt) {
        // K tile [128 keys][64 dim]; V^T tile [64 dim][128 keys]
#pragma unroll
        for (int i = 0; i < 8; ++i) {
            int f = tid + i * 256;
            int kr = f >> 4, kc = (f & 15) * 4;
            float4 kv = *(const float4*)(Kg + (size_t)(jt * 128 + kr) * HSIZE + kc);
            kv.x = __uint_as_float(f2tf32(kv.x)); kv.y = __uint_as_float(f2tf32(kv.y));
            kv.z = __uint_as_float(f2tf32(kv.z)); kv.w = __uint_as_float(f2tf32(kv.w));
            *(float4*)&Ks[kr * K_PAD + kc] = kv;
            int vr = f >> 5, vc = (f & 31) * 4;
            float4 vv = *(const float4*)(Vg + (size_t)vr * TSEQ + jt * 128 + vc);
            vv.x = __uint_as_float(f2tf32(vv.x)); vv.y = __uint_as_float(f2tf32(vv.y));
            vv.z = __uint_as_float(f2tf32(vv.z)); vv.w = __uint_as_float(f2tf32(vv.w));
            *(float4*)&Vs[vr * QP_PAD + vc] = vv;
        }
        __syncthreads();

        // S = Q K^T : 16 rows x 128 keys per warp
        float s[16][4];
#pragma unroll
        for (int nt = 0; nt < 16; ++nt)
#pragma unroll
            for (int j = 0; j < 4; ++j) s[nt][j] = 0.f;
#pragma unroll
        for (int kb = 0; kb < 8; ++kb) {
#pragma unroll
            for (int nt = 0; nt < 16; ++nt) {
                int n = nt * 8 + g;
                uint32_t b0 = __float_as_uint(Ks[n * K_PAD + kb * 8 + t]);
                uint32_t b1 = __float_as_uint(Ks[n * K_PAD + kb * 8 + t + 4]);
                mma_tf32(s[nt][0], s[nt][1], s[nt][2], s[nt][3],
                         qa[kb][0], qa[kb][1], qa[kb][2], qa[kb][3], b0, b1);
            }
        }

        // causal mask on the diagonal tile
        if (jt == qb) {
#pragma unroll
            for (int nt = 0; nt < 16; ++nt) {
                int col = jt * 128 + nt * 8 + 2 * t;
                if (col > row0)     s[nt][0] = -INFINITY;
                if (col + 1 > row0) s[nt][1] = -INFINITY;
                if (col > row1)     s[nt][2] = -INFINITY;
                if (col + 1 > row1) s[nt][3] = -INFINITY;
            }
        }

        // online softmax
        float mx0 = -INFINITY, mx1 = -INFINITY;
#pragma unroll
        for (int nt = 0; nt < 16; ++nt) {
            mx0 = fmaxf(mx0, fmaxf(s[nt][0], s[nt][1]));
            mx1 = fmaxf(mx1, fmaxf(s[nt][2], s[nt][3]));
        }
        mx0 = fmaxf(mx0, __shfl_xor_sync(0xffffffffu, mx0, 1));
        mx0 = fmaxf(mx0, __shfl_xor_sync(0xffffffffu, mx0, 2));
        mx1 = fmaxf(mx1, __shfl_xor_sync(0xffffffffu, mx1, 1));
        mx1 = fmaxf(mx1, __shfl_xor_sync(0xffffffffu, mx1, 2));
        float nm0 = fmaxf(m0, mx0), nm1 = fmaxf(m1, mx1);
        float cr0 = __expf(m0 - nm0), cr1 = __expf(m1 - nm1);
        l0 *= cr0; l1 *= cr1;
#pragma unroll
        for (int nt = 0; nt < 8; ++nt) {
            o[nt][0] *= cr0; o[nt][1] *= cr0;
            o[nt][2] *= cr1; o[nt][3] *= cr1;
        }
        float s0 = 0.f, s1 = 0.f;
#pragma unroll
        for (int nt = 0; nt < 16; ++nt) {
            float p00 = __expf(s[nt][0] - nm0);
            float p01 = __expf(s[nt][1] - nm0);
            float p10 = __expf(s[nt][2] - nm1);
            float p11 = __expf(s[nt][3] - nm1);
            s0 += p00 + p01; s1 += p10 + p11;
            float2 w0 = {__uint_as_float(f2tf32(p00)), __uint_as_float(f2tf32(p01))};
            float2 w1 = {__uint_as_float(f2tf32(p10)), __uint_as_float(f2tf32(p11))};
            *(float2*)&Ps[(mb + g) * QP_PAD + nt * 8 + 2 * t] = w0;
            *(float2*)&Ps[(mb + g + 8) * QP_PAD + nt * 8 + 2 * t] = w1;
        }
        s0 += __shfl_xor_sync(0xffffffffu, s0, 1);
        s0 += __shfl_xor_sync(0xffffffffu, s0, 2);
        s1 += __shfl_xor_sync(0xffffffffu, s1, 1);
        s1 += __shfl_xor_sync(0xffffffffu, s1, 2);
        l0 += s0; l1 += s1;
        m0 = nm0; m1 = nm1;
        __syncwarp();

        // O += P V : A = P (warp-private smem rows), B = V^T tile
#pragma unroll
        for (int kb = 0; kb < 16; ++kb) {
            uint32_t pa0 = __float_as_uint(Ps[(mb + g) * QP_PAD + kb * 8 + t]);
            uint32_t pa1 = __float_as_uint(Ps[(mb + g + 8) * QP_PAD + kb * 8 + t]);
            uint32_t pa2 = __float_as_uint(Ps[(mb + g) * QP_PAD + kb * 8 + t + 4]);
            uint32_t pa3 = __float_as_uint(Ps[(mb + g + 8) * QP_PAD + kb * 8 + t + 4]);
#pragma unroll
            for (int nt = 0; nt < 8; ++nt) {
                int n = nt * 8 + g;
                uint32_t b0 = __float_as_uint(Vs[n * QP_PAD + kb * 8 + t]);
                uint32_t b1 = __float_as_uint(Vs[n * QP_PAD + kb * 8 + t + 4]);
                mma_tf32(o[nt][0], o[nt][1], o[nt][2], o[nt][3],
                         pa0, pa1, pa2, pa3, b0, b1);
            }
        }
        __syncthreads();   // protect Ks/Vs (and Ps) before next tile
    }

    // write O -> g_attn [B*T, C]
    const int b = bh >> 4, h = bh & 15;
    const float inv0 = 1.f / l0, inv1 = 1.f / l1;
    float* O0 = g_attn + ((size_t)(b * TSEQ) + row0) * CEMB + h * HSIZE;
    float* O1 = g_attn + ((size_t)(b * TSEQ) + row1) * CEMB + h * HSIZE;
#pragma unroll
    for (int nt = 0; nt < 8; ++nt) {
        int d = nt * 8 + 2 * t;
        float2 v0 = {o[nt][0] * inv0, o[nt][1] * inv0};
        float2 v1 = {o[nt][2] * inv1, o[nt][3] * inv1};
        *(float2*)(O0 + d) = v0;
        *(float2*)(O1 + d) = v1;
    }
}

// ---------------------------------------------------------------------------
extern "C" void kernel_launch(void* const* d_in, const int* in_sizes, int n_in,
                              void* d_out, int out_size)
{
    const float* x      = (const float*)d_in[0];
    const float* w_qkv  = (const float*)d_in[1];
    const float* w_proj = (const float*)d_in[2];
    const float* b_proj = (const float*)d_in[3];
    float* out = (float*)d_out;

    float *attn_ptr = nullptr, *wtq = nullptr, *wtp = nullptr;
    cudaGetSymbolAddress((void**)&attn_ptr, g_attn);
    cudaGetSymbolAddress((void**)&wtq, g_wt_qkv);
    cudaGetSymbolAddress((void**)&wtp, g_wt_proj);

    const int ATTN_SMEM = (128 * QP_PAD + 128 * K_PAD + 64 * QP_PAD) * 4;  // 136192
    cudaFuncSetAttribute(attn_mma, cudaFuncAttributeMaxDynamicSharedMemorySize, ATTN_SMEM);

    // 0) transpose weights to K-major
    transpose_k<<<dim3(3 * CEMB / 32, CEMB / 32), dim3(32, 8)>>>(w_qkv, wtq, CEMB, 3 * CEMB);
    transpose_k<<<dim3(CEMB / 32, CEMB / 32), dim3(32, 8)>>>(w_proj, wtp, CEMB, CEMB);

    // 1) QKV GEMM + head-major scatter (V transposed)
    gemm_mma<<<dim3(3 * CEMB / 128, MROWS / 128), 256>>>(
        x, wtq, nullptr, nullptr, MROWS, 3 * CEMB, CEMB, 0);

    // 2) Causal flash attention (tf32 mma, 128-key tiles)
    attn_mma<<<dim3(TSEQ / 128, BATCH * NHEAD), 256, ATTN_SMEM>>>();

    // 3) Output projection + bias
    gemm_mma<<<dim3(CEMB / 128, MROWS / 128), 256>>>(
        attn_ptr, wtp, b_proj, out, MROWS, CEMB, CEMB, 1);
}

// round 6
// speedup vs baseline: 1.0765x; 1.0765x over previous
#include <cuda_runtime.h>
#include <math.h>
#include <stdint.h>

// Problem constants
#define BATCH   4
#define TSEQ    2048
#define NHEAD   16
#define HSIZE   64
#define CEMB    1024
#define MROWS   (BATCH*TSEQ)   // 8192

// Scratch (device globals: allocation-free rule)
__device__ float g_q[(size_t)BATCH * NHEAD * TSEQ * HSIZE];   // [B,H,T,D], q pre-scaled
__device__ float g_k[(size_t)BATCH * NHEAD * TSEQ * HSIZE];   // [B,H,T,D]
__device__ float g_v[(size_t)BATCH * NHEAD * TSEQ * HSIZE];   // [B,H,D,T]  (transposed!)
__device__ float g_attn[(size_t)MROWS * CEMB];                // [B*T, C]
__device__ float g_wt_qkv[(size_t)3 * CEMB * CEMB];           // [3C, C] K-major
__device__ float g_wt_proj[(size_t)CEMB * CEMB];              // [C, C]  K-major

// ---------------------------------------------------------------------------
// tf32 helpers
// ---------------------------------------------------------------------------
__device__ __forceinline__ uint32_t f2tf32(float x) {
    uint32_t r;
    asm("cvt.rna.tf32.f32 %0, %1;" : "=r"(r) : "f"(x));
    return r;
}
__device__ __forceinline__ void mma_tf32(float& c0, float& c1, float& c2, float& c3,
                                         uint32_t a0, uint32_t a1, uint32_t a2, uint32_t a3,
                                         uint32_t b0, uint32_t b1) {
    asm volatile("mma.sync.aligned.m16n8k8.row.col.f32.tf32.tf32.f32 "
                 "{%0,%1,%2,%3}, {%4,%5,%6,%7}, {%8,%9}, {%0,%1,%2,%3};"
                 : "+f"(c0), "+f"(c1), "+f"(c2), "+f"(c3)
                 : "r"(a0), "r"(a1), "r"(a2), "r"(a3), "r"(b0), "r"(b1));
}

// ---------------------------------------------------------------------------
// Weight transpose: in [R][C] row-major -> out [C][R] row-major
// ---------------------------------------------------------------------------
__global__ __launch_bounds__(256) void transpose_k(const float* __restrict__ in,
                                                   float* __restrict__ out, int R, int C)
{
    __shared__ float t[32][33];
    int bx = blockIdx.x * 32, by = blockIdx.y * 32;
#pragma unroll
    for (int i = 0; i < 32; i += 8)
        t[threadIdx.y + i][threadIdx.x] = in[(size_t)(by + threadIdx.y + i) * C + bx + threadIdx.x];
    __syncthreads();
#pragma unroll
    for (int i = 0; i < 32; i += 8)
        out[(size_t)(bx + threadIdx.y + i) * R + by + threadIdx.x] = t[threadIdx.x][threadIdx.y + i];
}

// ---------------------------------------------------------------------------
// tf32 GEMM via mma.sync, 128(M)x256(N) tile, double-buffered smem.
// 8 warps 4m x 2n: warp = 32 rows x 128 cols = 2(m16) x 16(n8) mma tiles.
// One __syncthreads per 32-wide K chunk; LDG for next chunk issued before
// compute, STS into the other buffer after compute.
// Smem layout (floats): per buffer: A[128][36] (4608) + B[256][36] (9216).
// Dyn smem = 2*13824*4 = 110592 B.
// mode 0: scatter g_q(x0.125)/g_k [B,H,T,D]; g_v [B,H,D,T]. mode 1: C=acc+bias.
// ---------------------------------------------------------------------------
#define GA_OFF 0
#define GB_OFF 4608
#define GBUF_STRIDE 13824
__global__ __launch_bounds__(256) void gemm_mma(
    const float* __restrict__ A, const float* __restrict__ Bt,
    const float* __restrict__ bias, float* __restrict__ C,
    int M, int N, int K, int mode)
{
    extern __shared__ float gsm[];

    const int tid  = threadIdx.x;
    const int wid  = tid >> 5;
    const int lane = tid & 31;
    const int g    = lane >> 2;
    const int t    = lane & 3;
    const int wm   = wid & 3;         // warp row: 32 rows
    const int wn   = wid >> 2;        // warp col: 128 cols
    const int m0 = blockIdx.y * 128;
    const int n0 = blockIdx.x * 256;

    const int lr = tid >> 3;          // A row 0..127 base / B row base
    const int lk = (tid & 7) * 4;     // k quad

    float c[2][16][4];
#pragma unroll
    for (int mt = 0; mt < 2; ++mt)
#pragma unroll
        for (int nt = 0; nt < 16; ++nt)
#pragma unroll
            for (int j = 0; j < 4; ++j) c[mt][nt][j] = 0.f;

    float4 pa[4], pb[8];

    // prologue: load + store chunk 0 into buffer 0
#pragma unroll
    for (int i = 0; i < 4; ++i)
        pa[i] = *(const float4*)(A + (size_t)(m0 + lr + i * 32) * K + lk);
#pragma unroll
    for (int i = 0; i < 8; ++i)
        pb[i] = *(const float4*)(Bt + (size_t)(n0 + lr + i * 32) * K + lk);
#pragma unroll
    for (int i = 0; i < 4; ++i) {
        float4 v = pa[i];
        v.x = __uint_as_float(f2tf32(v.x)); v.y = __uint_as_float(f2tf32(v.y));
        v.z = __uint_as_float(f2tf32(v.z)); v.w = __uint_as_float(f2tf32(v.w));
        *(float4*)&gsm[GA_OFF + (lr + i * 32) * 36 + lk] = v;
    }
#pragma unroll
    for (int i = 0; i < 8; ++i) {
        float4 v = pb[i];
        v.x = __uint_as_float(f2tf32(v.x)); v.y = __uint_as_float(f2tf32(v.y));
        v.z = __uint_as_float(f2tf32(v.z)); v.w = __uint_as_float(f2tf32(v.w));
        *(float4*)&gsm[GB_OFF + (lr + i * 32) * 36 + lk] = v;
    }
    __syncthreads();

    const int KS = K >> 5;
#pragma unroll 1
    for (int s = 0; s < KS; ++s) {
        const float* As = gsm + (s & 1) * GBUF_STRIDE + GA_OFF;
        const float* Bs = gsm + (s & 1) * GBUF_STRIDE + GB_OFF;

        // issue next chunk's LDGs (latency hidden behind compute)
        if (s + 1 < KS) {
            const int k1 = (s + 1) << 5;
#pragma unroll
            for (int i = 0; i < 4; ++i)
                pa[i] = *(const float4*)(A + (size_t)(m0 + lr + i * 32) * K + k1 + lk);
#pragma unroll
            for (int i = 0; i < 8; ++i)
                pb[i] = *(const float4*)(Bt + (size_t)(n0 + lr + i * 32) * K + k1 + lk);
        }

        // compute chunk s
#pragma unroll
        for (int kt = 0; kt < 4; ++kt) {
            const int kb = kt * 8;
            uint32_t bf[16][2];
#pragma unroll
            for (int nt = 0; nt < 16; ++nt) {
                int n = wn * 128 + nt * 8 + g;
                bf[nt][0] = __float_as_uint(Bs[n * 36 + kb + t]);
                bf[nt][1] = __float_as_uint(Bs[n * 36 + kb + t + 4]);
            }
#pragma unroll
            for (int mt = 0; mt < 2; ++mt) {
                int mb = wm * 32 + mt * 16;
                uint32_t a0 = __float_as_uint(As[(mb + g) * 36 + kb + t]);
                uint32_t a1 = __float_as_uint(As[(mb + g + 8) * 36 + kb + t]);
                uint32_t a2 = __float_as_uint(As[(mb + g) * 36 + kb + t + 4]);
                uint32_t a3 = __float_as_uint(As[(mb + g + 8) * 36 + kb + t + 4]);
#pragma unroll
                for (int nt = 0; nt < 16; ++nt)
                    mma_tf32(c[mt][nt][0], c[mt][nt][1], c[mt][nt][2], c[mt][nt][3],
                             a0, a1, a2, a3, bf[nt][0], bf[nt][1]);
            }
        }

        // store next chunk into the other buffer
        if (s + 1 < KS) {
            float* Ad = gsm + ((s + 1) & 1) * GBUF_STRIDE + GA_OFF;
            float* Bd = gsm + ((s + 1) & 1) * GBUF_STRIDE + GB_OFF;
#pragma unroll
            for (int i = 0; i < 4; ++i) {
                float4 v = pa[i];
                v.x = __uint_as_float(f2tf32(v.x)); v.y = __uint_as_float(f2tf32(v.y));
                v.z = __uint_as_float(f2tf32(v.z)); v.w = __uint_as_float(f2tf32(v.w));
                *(float4*)&Ad[(lr + i * 32) * 36 + lk] = v;
            }
#pragma unroll
            for (int i = 0; i < 8; ++i) {
                float4 v = pb[i];
                v.x = __uint_as_float(f2tf32(v.x)); v.y = __uint_as_float(f2tf32(v.y));
                v.z = __uint_as_float(f2tf32(v.z)); v.w = __uint_as_float(f2tf32(v.w));
                *(float4*)&Bd[(lr + i * 32) * 36 + lk] = v;
            }
        }
        __syncthreads();
    }

    // Epilogue. Warp cols span 128 -> head region varies per nt (mode 0).
    const int nwarp = n0 + wn * 128;
    if (mode == 0) {
#pragma unroll
        for (int mt = 0; mt < 2; ++mt) {
            int r0 = m0 + wm * 32 + mt * 16 + g;
            int bb0 = r0 >> 11, tt0 = r0 & (TSEQ - 1);
            int r1 = r0 + 8;
            int bb1 = r1 >> 11, tt1 = r1 & (TSEQ - 1);
#pragma unroll
            for (int nt = 0; nt < 16; ++nt) {
                int n = nwarp + nt * 8;
                int which = n >> 10;
                int h = (n & 1023) >> 6;
                int d = (n & 63) + 2 * t;
                if (which == 2) {
                    float* base0 = g_v + ((size_t)(bb0 * NHEAD + h)) * HSIZE * TSEQ;
                    float* base1 = g_v + ((size_t)(bb1 * NHEAD + h)) * HSIZE * TSEQ;
                    base0[(size_t)d * TSEQ + tt0]       = c[mt][nt][0];
                    base0[(size_t)(d + 1) * TSEQ + tt0] = c[mt][nt][1];
                    base1[(size_t)d * TSEQ + tt1]       = c[mt][nt][2];
                    base1[(size_t)(d + 1) * TSEQ + tt1] = c[mt][nt][3];
                } else {
                    const float sc = (which == 0) ? 0.125f : 1.0f;
                    float* base = (which == 0) ? g_q : g_k;
                    float* d0 = base + (((size_t)(bb0 * NHEAD + h) * TSEQ) + tt0) * HSIZE + d;
                    float* d1 = base + (((size_t)(bb1 * NHEAD + h) * TSEQ) + tt1) * HSIZE + d;
                    float2 v0 = {c[mt][nt][0] * sc, c[mt][nt][1] * sc};
                    float2 v1 = {c[mt][nt][2] * sc, c[mt][nt][3] * sc};
                    *(float2*)d0 = v0;
                    *(float2*)d1 = v1;
                }
            }
        }
    } else {
#pragma unroll
        for (int mt = 0; mt < 2; ++mt) {
            int r0 = m0 + wm * 32 + mt * 16 + g;
#pragma unroll
            for (int nt = 0; nt < 16; ++nt) {
                int n = nwarp + nt * 8 + 2 * t;
                float2 bv = *(const float2*)(bias + n);
                float2 v0 = {c[0 + mt][nt][0] + bv.x, c[mt][nt][1] + bv.y};
                float2 v1 = {c[mt][nt][2] + bv.x, c[mt][nt][3] + bv.y};
                *(float2*)(C + (size_t)r0 * N + n) = v0;
                *(float2*)(C + (size_t)(r0 + 8) * N + n) = v1;
            }
        }
    }
}

// ---------------------------------------------------------------------------
// Tensor-core causal flash attention (tf32 mma.sync), 128-key tiles.
// (unchanged from round 5 — 352 us, known correct)
// ---------------------------------------------------------------------------
#define QP_PAD 132
#define K_PAD  68
__global__ __launch_bounds__(256) void attn_mma()
{
    extern __shared__ float sm[];
    float* Qs = sm;                        // [128][QP_PAD]  (aliased by Ps)
    float* Ks = sm + 128 * QP_PAD;         // [128][K_PAD]
    float* Vs = Ks + 128 * K_PAD;          // [64][QP_PAD]
    float* Ps = Qs;

    const int tid  = threadIdx.x;
    const int wid  = tid >> 5;
    const int lane = tid & 31;
    const int g    = lane >> 2;
    const int t    = lane & 3;
    const int mb   = wid * 16;
    const int bh   = blockIdx.y;
    const int qb   = gridDim.x - 1 - blockIdx.x;
    const int q0   = qb * 128;

    const float* Qg = g_q + ((size_t)bh * TSEQ + q0) * HSIZE;
#pragma unroll
    for (int i = 0; i < 8; ++i) {
        int f = tid + i * 256;
        int r = f >> 4, c4 = (f & 15) * 4;
        float4 v = *(const float4*)(Qg + (size_t)r * HSIZE + c4);
        v.x = __uint_as_float(f2tf32(v.x)); v.y = __uint_as_float(f2tf32(v.y));
        v.z = __uint_as_float(f2tf32(v.z)); v.w = __uint_as_float(f2tf32(v.w));
        *(float4*)&Qs[r * QP_PAD + c4] = v;
    }
    __syncthreads();

    uint32_t qa[8][4];
#pragma unroll
    for (int kb = 0; kb < 8; ++kb) {
        qa[kb][0] = __float_as_uint(Qs[(mb + g) * QP_PAD + kb * 8 + t]);
        qa[kb][1] = __float_as_uint(Qs[(mb + g + 8) * QP_PAD + kb * 8 + t]);
        qa[kb][2] = __float_as_uint(Qs[(mb + g) * QP_PAD + kb * 8 + t + 4]);
        qa[kb][3] = __float_as_uint(Qs[(mb + g + 8) * QP_PAD + kb * 8 + t + 4]);
    }
    __syncthreads();

    float o[8][4];
#pragma unroll
    for (int nt = 0; nt < 8; ++nt)
#pragma unroll
        for (int j = 0; j < 4; ++j) o[nt][j] = 0.f;
    float m0 = -INFINITY, m1 = -INFINITY, l0 = 0.f, l1 = 0.f;

    const int row0 = q0 + mb + g;
    const int row1 = row0 + 8;

    const float* Kg = g_k + (size_t)bh * TSEQ * HSIZE;
    const float* Vg = g_v + (size_t)bh * HSIZE * TSEQ;

    for (int jt = 0; jt <= qb; ++jt) {
#pragma unroll
        for (int i = 0; i < 8; ++i) {
            int f = tid + i * 256;
            int kr = f >> 4, kc = (f & 15) * 4;
            float4 kv = *(const float4*)(Kg + (size_t)(jt * 128 + kr) * HSIZE + kc);
            kv.x = __uint_as_float(f2tf32(kv.x)); kv.y = __uint_as_float(f2tf32(kv.y));
            kv.z = __uint_as_float(f2tf32(kv.z)); kv.w = __uint_as_float(f2tf32(kv.w));
            *(float4*)&Ks[kr * K_PAD + kc] = kv;
            int vr = f >> 5, vc = (f & 31) * 4;
            float4 vv = *(const float4*)(Vg + (size_t)vr * TSEQ + jt * 128 + vc);
            vv.x = __uint_as_float(f2tf32(vv.x)); vv.y = __uint_as_float(f2tf32(vv.y));
            vv.z = __uint_as_float(f2tf32(vv.z)); vv.w = __uint_as_float(f2tf32(vv.w));
            *(float4*)&Vs[vr * QP_PAD + vc] = vv;
        }
        __syncthreads();

        float s[16][4];
#pragma unroll
        for (int nt = 0; nt < 16; ++nt)
#pragma unroll
            for (int j = 0; j < 4; ++j) s[nt][j] = 0.f;
#pragma unroll
        for (int kb = 0; kb < 8; ++kb) {
#pragma unroll
            for (int nt = 0; nt < 16; ++nt) {
                int n = nt * 8 + g;
                uint32_t b0 = __float_as_uint(Ks[n * K_PAD + kb * 8 + t]);
                uint32_t b1 = __float_as_uint(Ks[n * K_PAD + kb * 8 + t + 4]);
                mma_tf32(s[nt][0], s[nt][1], s[nt][2], s[nt][3],
                         qa[kb][0], qa[kb][1], qa[kb][2], qa[kb][3], b0, b1);
            }
        }

        if (jt == qb) {
#pragma unroll
            for (int nt = 0; nt < 16; ++nt) {
                int col = jt * 128 + nt * 8 + 2 * t;
                if (col > row0)     s[nt][0] = -INFINITY;
                if (col + 1 > row0) s[nt][1] = -INFINITY;
                if (col > row1)     s[nt][2] = -INFINITY;
                if (col + 1 > row1) s[nt][3] = -INFINITY;
            }
        }

        float mx0 = -INFINITY, mx1 = -INFINITY;
#pragma unroll
        for (int nt = 0; nt < 16; ++nt) {
            mx0 = fmaxf(mx0, fmaxf(s[nt][0], s[nt][1]));
            mx1 = fmaxf(mx1, fmaxf(s[nt][2], s[nt][3]));
        }
        mx0 = fmaxf(mx0, __shfl_xor_sync(0xffffffffu, mx0, 1));
        mx0 = fmaxf(mx0, __shfl_xor_sync(0xffffffffu, mx0, 2));
        mx1 = fmaxf(mx1, __shfl_xor_sync(0xffffffffu, mx1, 1));
        mx1 = fmaxf(mx1, __shfl_xor_sync(0xffffffffu, mx1, 2));
        float nm0 = fmaxf(m0, mx0), nm1 = fmaxf(m1, mx1);
        float cr0 = __expf(m0 - nm0), cr1 = __expf(m1 - nm1);
        l0 *= cr0; l1 *= cr1;
#pragma unroll
        for (int nt = 0; nt < 8; ++nt) {
            o[nt][0] *= cr0; o[nt][1] *= cr0;
            o[nt][2] *= cr1; o[nt][3] *= cr1;
        }
        float s0 = 0.f, s1 = 0.f;
#pragma unroll
        for (int nt = 0; nt < 16; ++nt) {
            float p00 = __expf(s[nt][0] - nm0);
            float p01 = __expf(s[nt][1] - nm0);
            float p10 = __expf(s[nt][2] - nm1);
            float p11 = __expf(s[nt][3] - nm1);
            s0 += p00 + p01; s1 += p10 + p11;
            float2 w0 = {__uint_as_float(f2tf32(p00)), __uint_as_float(f2tf32(p01))};
            float2 w1 = {__uint_as_float(f2tf32(p10)), __uint_as_float(f2tf32(p11))};
            *(float2*)&Ps[(mb + g) * QP_PAD + nt * 8 + 2 * t] = w0;
            *(float2*)&Ps[(mb + g + 8) * QP_PAD + nt * 8 + 2 * t] = w1;
        }
        s0 += __shfl_xor_sync(0xffffffffu, s0, 1);
        s0 += __shfl_xor_sync(0xffffffffu, s0, 2);
        s1 += __shfl_xor_sync(0xffffffffu, s1, 1);
        s1 += __shfl_xor_sync(0xffffffffu, s1, 2);
        l0 += s0; l1 += s1;
        m0 = nm0; m1 = nm1;
        __syncwarp();

#pragma unroll
        for (int kb = 0; kb < 16; ++kb) {
            uint32_t pa0 = __float_as_uint(Ps[(mb + g) * QP_PAD + kb * 8 + t]);
            uint32_t pa1 = __float_as_uint(Ps[(mb + g + 8) * QP_PAD + kb * 8 + t]);
            uint32_t pa2 = __float_as_uint(Ps[(mb + g) * QP_PAD + kb * 8 + t + 4]);
            uint32_t pa3 = __float_as_uint(Ps[(mb + g + 8) * QP_PAD + kb * 8 + t + 4]);
#pragma unroll
            for (int nt = 0; nt < 8; ++nt) {
                int n = nt * 8 + g;
                uint32_t b0 = __float_as_uint(Vs[n * QP_PAD + kb * 8 + t]);
                uint32_t b1 = __float_as_uint(Vs[n * QP_PAD + kb * 8 + t + 4]);
                mma_tf32(o[nt][0], o[nt][1], o[nt][2], o[nt][3],
                         pa0, pa1, pa2, pa3, b0, b1);
            }
        }
        __syncthreads();
    }

    const int b = bh >> 4, h = bh & 15;
    const float inv0 = 1.f / l0, inv1 = 1.f / l1;
    float* O0 = g_attn + ((size_t)(b * TSEQ) + row0) * CEMB + h * HSIZE;
    float* O1 = g_attn + ((size_t)(b * TSEQ) + row1) * CEMB + h * HSIZE;
#pragma unroll
    for (int nt = 0; nt < 8; ++nt) {
        int d = nt * 8 + 2 * t;
        float2 v0 = {o[nt][0] * inv0, o[nt][1] * inv0};
        float2 v1 = {o[nt][2] * inv1, o[nt][3] * inv1};
        *(float2*)(O0 + d) = v0;
        *(float2*)(O1 + d) = v1;
    }
}

// ---------------------------------------------------------------------------
extern "C" void kernel_launch(void* const* d_in, const int* in_sizes, int n_in,
                              void* d_out, int out_size)
{
    const float* x      = (const float*)d_in[0];
    const float* w_qkv  = (const float*)d_in[1];
    const float* w_proj = (const float*)d_in[2];
    const float* b_proj = (const float*)d_in[3];
    float* out = (float*)d_out;

    float *attn_ptr = nullptr, *wtq = nullptr, *wtp = nullptr;
    cudaGetSymbolAddress((void**)&attn_ptr, g_attn);
    cudaGetSymbolAddress((void**)&wtq, g_wt_qkv);
    cudaGetSymbolAddress((void**)&wtp, g_wt_proj);

    const int ATTN_SMEM = (128 * QP_PAD + 128 * K_PAD + 64 * QP_PAD) * 4;  // 136192
    const int GEMM_SMEM = 2 * GBUF_STRIDE * 4;                             // 110592
    cudaFuncSetAttribute(attn_mma, cudaFuncAttributeMaxDynamicSharedMemorySize, ATTN_SMEM);
    cudaFuncSetAttribute(gemm_mma, cudaFuncAttributeMaxDynamicSharedMemorySize, GEMM_SMEM);

    // 0) transpose weights to K-major
    transpose_k<<<dim3(3 * CEMB / 32, CEMB / 32), dim3(32, 8)>>>(w_qkv, wtq, CEMB, 3 * CEMB);
    transpose_k<<<dim3(CEMB / 32, CEMB / 32), dim3(32, 8)>>>(w_proj, wtp, CEMB, CEMB);

    // 1) QKV GEMM + head-major scatter (V transposed)
    gemm_mma<<<dim3(3 * CEMB / 256, MROWS / 128), 256, GEMM_SMEM>>>(
        x, wtq, nullptr, nullptr, MROWS, 3 * CEMB, CEMB, 0);

    // 2) Causal flash attention (tf32 mma, 128-key tiles)
    attn_mma<<<dim3(TSEQ / 128, BATCH * NHEAD), 256, ATTN_SMEM>>>();

    // 3) Output projection + bias
    gemm_mma<<<dim3(CEMB / 256, MROWS / 128), 256, GEMM_SMEM>>>(
        attn_ptr, wtp, b_proj, out, MROWS, CEMB, CEMB, 1);
}